// round 4
// baseline (speedup 1.0000x reference)
#include <cuda_runtime.h>
#include <cuda_bf16.h>

// Problem constants
#define BB   512
#define SS   1024
#define FIN  16      // features per (b,s); feature 15 is delta
#define HH   64
#define GG   192     // 3*H
#define NB   2       // batches per CTA
#define NT   256     // 8 warps; thread = (j in [0,64), q in [0,4) k-quarter)
#define NCTA (BB/NB) // 256 -> 2 CTAs per SM on most SMs

typedef unsigned long long u64;

// ---- packed f32x2 helpers (bit-exact fp32, 2 FMA per fma-pipe slot) ----
__device__ __forceinline__ u64 pack2(float lo, float hi) {
    u64 r; asm("mov.b64 %0, {%1, %2};" : "=l"(r) : "f"(lo), "f"(hi)); return r;
}
__device__ __forceinline__ void unpack2(u64 v, float& lo, float& hi) {
    asm("mov.b64 {%0, %1}, %2;" : "=f"(lo), "=f"(hi) : "l"(v));
}
__device__ __forceinline__ u64 fma2(u64 a, u64 b, u64 c) {
    u64 d; asm("fma.rn.f32x2 %0, %1, %2, %3;" : "=l"(d) : "l"(a), "l"(b), "l"(c)); return d;
}

__device__ __forceinline__ float sigmoidf_(float x) {
    return __fdividef(1.0f, 1.0f + __expf(-x));
}
__device__ __forceinline__ float tanhf_(float x) {
    return __fdividef(2.0f, 1.0f + __expf(-2.0f * x)) - 1.0f;
}

__global__ __launch_bounds__(NT, 2)
void gru_scan_kernel(const float* __restrict__ inputs,   // (B,S,16)
                     const float* __restrict__ k_in,     // (15,192)
                     const float* __restrict__ r_in,     // (64,192)
                     const float* __restrict__ bias,     // (2,192)
                     const float* __restrict__ w1,       // (64,64)
                     const float* __restrict__ b1,       // (64)
                     const float* __restrict__ bn_gamma,
                     const float* __restrict__ bn_beta,
                     const float* __restrict__ bn_mean,
                     const float* __restrict__ bn_var,
                     const float* __restrict__ w2,       // (64,1)
                     const float* __restrict__ b2,       // (1)
                     const float* __restrict__ Tp,       // (1)
                     float* __restrict__ out)            // (B,1)
{
    __shared__ __align__(16) float sm_h[2][NB][HH];   // double-buffered hidden state
    __shared__ __align__(16) float sm_x[2][NB][FIN];  // double-buffered step inputs
    __shared__ float sm_d[NB];
    __shared__ float sm_e[NB][HH];

    const int tid   = threadIdx.x;
    const int lane  = tid & 31;
    const int warp  = tid >> 5;
    const int j     = warp * 8 + (lane & 7);  // column triple owner: 0..63
    const int q     = lane >> 3;              // k-quarter: 0..3
    const int bbase = blockIdx.x * NB;

    // ---- Per-thread weights: 3 gate columns (z,r,h) restricted to k in [16q,16q+16) ----
    const int gz = j, gr = j + HH, gh = j + 2 * HH;
    u64 Rz[8], Rr[8], Rh[8];
    #pragma unroll
    for (int t = 0; t < 8; t++) {
        int k = 16 * q + 2 * t;
        Rz[t] = pack2(r_in[k * GG + gz], r_in[(k + 1) * GG + gz]);
        Rr[t] = pack2(r_in[k * GG + gr], r_in[(k + 1) * GG + gr]);
        Rh[t] = pack2(r_in[k * GG + gh], r_in[(k + 1) * GG + gh]);
    }
    // x-projection weights: features f in [4q, 4q+4); feature 15 (delta) masked to 0
    u64 Kz[2], Kr[2], Kh[2];
    #pragma unroll
    for (int t = 0; t < 2; t++) {
        int f = 4 * q + 2 * t;
        float z1 = (f + 1 < 15) ? k_in[(f + 1) * GG + gz] : 0.0f;
        float r1 = (f + 1 < 15) ? k_in[(f + 1) * GG + gr] : 0.0f;
        float h1 = (f + 1 < 15) ? k_in[(f + 1) * GG + gh] : 0.0f;
        Kz[t] = pack2(k_in[f * GG + gz], z1);
        Kr[t] = pack2(k_in[f * GG + gr], r1);
        Kh[t] = pack2(k_in[f * GG + gh], h1);
    }
    // biases per owned column triple (z,r merge input+recurrent bias; h keeps them split)
    const float bzr = bias[gz] + bias[GG + gz];
    const float brr = bias[gr] + bias[GG + gr];
    const float bih = bias[gh];
    const float brh = bias[GG + gh];

    // init both h buffers to 0 (256 floats over 256 threads)
    ((float*)sm_h)[tid] = 0.0f;
    // preload x for s=0 into buffer 0
    if (tid < NB * 4) {
        int b = tid >> 2, qq = tid & 3;
        ((float4*)sm_x[0][b])[qq] =
            *(const float4*)&inputs[(size_t)(bbase + b) * SS * FIN + (size_t)qq * 4];
    }
    float dsum = 0.0f;
    __syncthreads();

    for (int s = 0; s < SS; s++) {
        const int p = s & 1;

        // prefetch next step's x into the other buffer (safe: one barrier behind)
        if (s + 1 < SS && tid < NB * 4) {
            int b = tid >> 2, qq = tid & 3;
            ((float4*)sm_x[p ^ 1][b])[qq] =
                *(const float4*)&inputs[((size_t)(bbase + b) * SS + (s + 1)) * FIN +
                                        (size_t)qq * 4];
        }
        if (tid < NB) dsum += sm_x[p][tid][15];   // delta accumulation (free)

        // ---------- partial dots over this thread's k-quarter ----------
        float sz[NB], sr[NB], sxh[NB], srh[NB];
        #pragma unroll
        for (int b = 0; b < NB; b++) {
            const ulonglong2* hp = (const ulonglong2*)&sm_h[p][b][16 * q];
            u64 az = 0ull, ar = 0ull, ah = 0ull, ax = 0ull;
            #pragma unroll
            for (int t2 = 0; t2 < 4; t2++) {
                ulonglong2 hv = hp[t2];                 // LDS.128, 8-way broadcast
                az = fma2(hv.x, Rz[2 * t2],     az);
                ar = fma2(hv.x, Rr[2 * t2],     ar);
                ah = fma2(hv.x, Rh[2 * t2],     ah);
                az = fma2(hv.y, Rz[2 * t2 + 1], az);
                ar = fma2(hv.y, Rr[2 * t2 + 1], ar);
                ah = fma2(hv.y, Rh[2 * t2 + 1], ah);
            }
            ulonglong2 xv = *(const ulonglong2*)&sm_x[p][b][4 * q];
            az = fma2(xv.x, Kz[0], az);
            ar = fma2(xv.x, Kr[0], ar);
            ax = fma2(xv.x, Kh[0], ax);
            az = fma2(xv.y, Kz[1], az);
            ar = fma2(xv.y, Kr[1], ar);
            ax = fma2(xv.y, Kh[1], ax);

            float lo, hi;
            unpack2(az, lo, hi); sz[b]  = lo + hi;
            unpack2(ar, lo, hi); sr[b]  = lo + hi;
            unpack2(ah, lo, hi); srh[b] = lo + hi;
            unpack2(ax, lo, hi); sxh[b] = lo + hi;
        }

        // ---------- cross-quarter butterfly reduction (all lanes get totals) ----------
        #pragma unroll
        for (int b = 0; b < NB; b++) {
            sz[b]  += __shfl_xor_sync(0xffffffffu, sz[b],  8);
            sz[b]  += __shfl_xor_sync(0xffffffffu, sz[b],  16);
            sr[b]  += __shfl_xor_sync(0xffffffffu, sr[b],  8);
            sr[b]  += __shfl_xor_sync(0xffffffffu, sr[b],  16);
            sxh[b] += __shfl_xor_sync(0xffffffffu, sxh[b], 8);
            sxh[b] += __shfl_xor_sync(0xffffffffu, sxh[b], 16);
            srh[b] += __shfl_xor_sync(0xffffffffu, srh[b], 8);
            srh[b] += __shfl_xor_sync(0xffffffffu, srh[b], 16);
        }

        // ---------- gates: lanes 0..15, lane = (batch, j) task ----------
        if (lane < 16) {
            int bt = lane >> 3;
            float ho = sm_h[p][bt][j];
            float z  = sigmoidf_(sz[bt] + bzr);
            float r  = sigmoidf_(sr[bt] + brr);
            float hh = tanhf_((sxh[bt] + bih) + r * (srh[bt] + brh));
            sm_h[p ^ 1][bt][j] = z * (ho - hh) + hh;
        }
        __syncthreads();   // the ONLY barrier per step
    }

    // ---------- Epilogue: delta effect + MLP head + BN ----------
    if (tid < NB) sm_d[tid] = Tp[0] * dsum * (1.0f / (float)SS);
    __syncthreads();

    if (tid < NB * HH) {
        int b = tid >> 6, jj = tid & 63;
        float db  = sm_d[b];
        float acc = b1[jj];
        #pragma unroll 8
        for (int k = 0; k < HH; k++)
            acc += (sm_h[0][b][k] + db) * w1[k * HH + jj];   // final h is in buffer 0
        float hr = fmaxf(acc, 0.0f);
        float hb = (hr - bn_mean[jj]) * rsqrtf(bn_var[jj] + 1e-3f) * bn_gamma[jj] + bn_beta[jj];
        sm_e[b][jj] = hb * w2[jj];
    }
    __syncthreads();

    if (tid < NB) {
        float acc = b2[0];
        #pragma unroll 8
        for (int jj = 0; jj < HH; jj++) acc += sm_e[tid][jj];
        out[bbase + tid] = acc;
    }
}

extern "C" void kernel_launch(void* const* d_in, const int* in_sizes, int n_in,
                              void* d_out, int out_size) {
    const float* inputs   = (const float*)d_in[0];
    const float* gk       = (const float*)d_in[1];
    const float* grk      = (const float*)d_in[2];
    const float* gbias    = (const float*)d_in[3];
    const float* w1       = (const float*)d_in[4];
    const float* b1       = (const float*)d_in[5];
    const float* bn_gamma = (const float*)d_in[6];
    const float* bn_beta  = (const float*)d_in[7];
    const float* bn_mean  = (const float*)d_in[8];
    const float* bn_var   = (const float*)d_in[9];
    const float* w2       = (const float*)d_in[10];
    const float* b2       = (const float*)d_in[11];
    const float* T        = (const float*)d_in[12];
    float* out = (float*)d_out;

    gru_scan_kernel<<<NCTA, NT>>>(inputs, gk, grk, gbias, w1, b1,
                                  bn_gamma, bn_beta, bn_mean, bn_var,
                                  w2, b2, T, out);
}